// round 7
// baseline (speedup 1.0000x reference)
#include <cuda_runtime.h>
#include <cstdint>

// Problem dims (fixed)
#define N_ROWS 8192
#define O_COLS 4096
#define K_DIM  4096

// GEMM tiling
#define KB 128                      // K bytes (int8 elems) per chunk
#define NCHUNK (K_DIM / KB)         // 32
#define MT 256                      // CTA M tile (x rows)
#define NT 128                      // CTA N tile (W rows / out cols)
#define STAGES 4
#define A_STAGE (MT * KB)           // 32768
#define B_STAGE (NT * KB)           // 16384
#define STAGE_BYTES (A_STAGE + B_STAGE)      // 49152
#define SMEM_BYTES (STAGES * STAGE_BYTES)    // 196608
#define GEMM_THREADS 512

// ---- scratch (device globals; no dynamic allocation allowed) ----
__device__ __align__(16) int8_t x8_g[(size_t)N_ROWS * K_DIM];   // 33.5 MB
__device__ __align__(16) int8_t w8_g[(size_t)O_COLS * K_DIM];   // 16.8 MB
__device__ float psum_g[8192];
__device__ float mean_g;

// ============================================================
// helpers
// ============================================================
__device__ __forceinline__ uint32_t smem_u32(const void* p) {
    uint32_t a;
    asm("{ .reg .u64 t; cvta.to.shared.u64 t, %1; cvt.u32.u64 %0, t; }" : "=r"(a) : "l"(p));
    return a;
}
__device__ __forceinline__ void cp16(uint32_t s, const void* g) {
    asm volatile("cp.async.cg.shared.global [%0], [%1], 16;" :: "r"(s), "l"(g) : "memory");
}
__device__ __forceinline__ void cp_commit() { asm volatile("cp.async.commit_group;" ::: "memory"); }
__device__ __forceinline__ void cp_wait2()  { asm volatile("cp.async.wait_group 2;" ::: "memory"); }

#define LDSM_X4(r0, r1, r2, r3, addr) \
    asm volatile("ldmatrix.sync.aligned.m8n8.x4.shared.b16 {%0,%1,%2,%3}, [%4];" \
                 : "=r"(r0), "=r"(r1), "=r"(r2), "=r"(r3) : "r"(addr))
#define LDSM_X2(r0, r1, addr) \
    asm volatile("ldmatrix.sync.aligned.m8n8.x2.shared.b16 {%0,%1}, [%2];" \
                 : "=r"(r0), "=r"(r1) : "r"(addr))

#define IMMA(d, a, b) \
    asm volatile("mma.sync.aligned.m16n8k32.row.col.s32.s8.s8.s32 " \
                 "{%0,%1,%2,%3}, {%4,%5,%6,%7}, {%8,%9}, {%0,%1,%2,%3};" \
                 : "+r"((d)[0]), "+r"((d)[1]), "+r"((d)[2]), "+r"((d)[3]) \
                 : "r"((a)[0]), "r"((a)[1]), "r"((a)[2]), "r"((a)[3]), \
                   "r"((b)[0]), "r"((b)[1]))

__device__ __forceinline__ int8_t s8sign(float v) {
    return (int8_t)((v > 0.f) - (v < 0.f));
}

// ============================================================
// convert x -> int8 sign + deterministic per-block |x| sums
// grid 8192 x 256 threads, 16 elems/thread
// ============================================================
__global__ void convert_x_kernel(const float* __restrict__ x) {
    const int tid = threadIdx.x;
    const size_t base = ((size_t)blockIdx.x * 256 + tid) * 16;
    float s = 0.f;
    union { uint4 u; int8_t b[16]; } pk;
    #pragma unroll
    for (int q = 0; q < 4; q++) {
        const float4 a = *(const float4*)(x + base + q * 4);
        s += fabsf(a.x) + fabsf(a.y) + fabsf(a.z) + fabsf(a.w);
        pk.b[q * 4 + 0] = s8sign(a.x); pk.b[q * 4 + 1] = s8sign(a.y);
        pk.b[q * 4 + 2] = s8sign(a.z); pk.b[q * 4 + 3] = s8sign(a.w);
    }
    *(uint4*)(x8_g + base) = pk.u;

    __shared__ float red[256];
    red[tid] = s;
    __syncthreads();
    #pragma unroll
    for (int off = 128; off > 0; off >>= 1) {
        if (tid < off) red[tid] += red[tid + off];
        __syncthreads();
    }
    if (tid == 0) psum_g[blockIdx.x] = red[0];
}

// grid 4096 x 256 threads
__global__ void convert_w_kernel(const float* __restrict__ W) {
    const int tid = threadIdx.x;
    const size_t base = ((size_t)blockIdx.x * 256 + tid) * 16;
    union { uint4 u; int8_t b[16]; } pk;
    #pragma unroll
    for (int q = 0; q < 4; q++) {
        const float4 a = *(const float4*)(W + base + q * 4);
        pk.b[q * 4 + 0] = s8sign(a.x); pk.b[q * 4 + 1] = s8sign(a.y);
        pk.b[q * 4 + 2] = s8sign(a.z); pk.b[q * 4 + 3] = s8sign(a.w);
    }
    *(uint4*)(w8_g + base) = pk.u;
}

__global__ void reduce_mean_kernel() {
    __shared__ float red[1024];
    const int tid = threadIdx.x;
    float s = 0.f;
    for (int i = tid; i < 8192; i += 1024) s += psum_g[i];
    red[tid] = s;
    __syncthreads();
    #pragma unroll
    for (int off = 512; off > 0; off >>= 1) {
        if (tid < off) red[tid] += red[tid + off];
        __syncthreads();
    }
    if (tid == 0) mean_g = red[0] * (1.0f / ((float)N_ROWS * (float)K_DIM));
}

// ============================================================
// int8 IMMA GEMM: 256x128 CTA tile, 4-stage cp.async pipeline.
// out[m,n] = (sum_k xs[m,k]*ws[n,k] + b[n]) * mean
// smem rows are 128B with SW128 XOR swizzle: seg' = seg ^ (row&7).
// ============================================================
__global__ __launch_bounds__(GEMM_THREADS, 1)
void imma_gemm_kernel(const float* __restrict__ bias, float* __restrict__ out) {
    extern __shared__ __align__(1024) char smem[];
    const uint32_t sb = smem_u32(smem);
    const int tid  = threadIdx.x;
    const int wid  = tid >> 5;
    const int lane = tid & 31;

    const int m0 = blockIdx.y * MT;
    const int n0 = blockIdx.x * NT;
    const int8_t* gA = x8_g + (size_t)m0 * K_DIM;
    const int8_t* gB = w8_g + (size_t)n0 * K_DIM;

    // ---- loader geometry: each thread cp16's rows lrow+64i, 16B seg lseg
    const int lrow = tid >> 3;          // 0..63
    const int lseg = tid & 7;           // 0..7
    uint32_t sA[4], sB[2];
    #pragma unroll
    for (int i = 0; i < 4; i++) {
        const int r = lrow + 64 * i;
        sA[i] = (uint32_t)r * 128u + (uint32_t)((lseg ^ (r & 7)) << 4);
    }
    #pragma unroll
    for (int i = 0; i < 2; i++) {
        const int r = lrow + 64 * i;
        sB[i] = (uint32_t)r * 128u + (uint32_t)((lseg ^ (r & 7)) << 4);
    }

    // ---- compute geometry: 4x4 warps, warp tile 64(m) x 32(n)
    const int wm = wid >> 2;            // 0..3
    const int wn = wid & 3;             // 0..3
    // A ldmatrix rows: am-atom -> row wm*64 + am*16 + (lane&15); k-seg = lane>>4
    uint32_t aRow128[4]; int aMask[4];
    #pragma unroll
    for (int am = 0; am < 4; am++) {
        const int r = wm * 64 + am * 16 + (lane & 15);
        aRow128[am] = (uint32_t)r * 128u;
        aMask[am] = r & 7;
    }
    const int aKseg = lane >> 4;        // 0/1
    // B ldmatrix rows: bn-atom -> row wn*32 + bn*8 + (lane&7); k-seg = (lane>>3)&1
    uint32_t bRow128[4]; int bMask[4];
    #pragma unroll
    for (int bn = 0; bn < 4; bn++) {
        const int r = wn * 32 + bn * 8 + (lane & 7);
        bRow128[bn] = (uint32_t)r * 128u;
        bMask[bn] = r & 7;
    }
    const int bKseg = (lane >> 3) & 1;  // 0/1 (lanes 16-31 unused by x2 but harmless)

    int acc[4][4][4];
    #pragma unroll
    for (int i = 0; i < 4; i++)
        #pragma unroll
        for (int j = 0; j < 4; j++)
            #pragma unroll
            for (int q = 0; q < 4; q++) acc[i][j][q] = 0;

    // ---- prologue: load chunks 0,1,2
    #pragma unroll
    for (int c = 0; c < 3; c++) {
        const uint32_t st = sb + (uint32_t)c * STAGE_BYTES;
        const int8_t* a = gA + c * KB + lseg * 16;
        const int8_t* b = gB + c * KB + lseg * 16;
        #pragma unroll
        for (int i = 0; i < 4; i++) cp16(st + sA[i], a + (size_t)(lrow + 64 * i) * K_DIM);
        #pragma unroll
        for (int i = 0; i < 2; i++) cp16(st + A_STAGE + sB[i], b + (size_t)(lrow + 64 * i) * K_DIM);
        cp_commit();
    }

    // ---- main loop
    #pragma unroll 1
    for (int k = 0; k < NCHUNK; k++) {
        cp_wait2();          // stage k arrived (3 in flight -> oldest done)
        __syncthreads();     // stage (k-1)&3 fully consumed by all warps

        // issue chunk k+3 into stage (k+3)&3 (empty commit in tail keeps counts)
        if (k + 3 < NCHUNK) {
            const uint32_t st = sb + (uint32_t)((k + 3) & 3) * STAGE_BYTES;
            const int8_t* a = gA + (k + 3) * KB + lseg * 16;
            const int8_t* b = gB + (k + 3) * KB + lseg * 16;
            #pragma unroll
            for (int i = 0; i < 4; i++) cp16(st + sA[i], a + (size_t)(lrow + 64 * i) * K_DIM);
            #pragma unroll
            for (int i = 0; i < 2; i++) cp16(st + A_STAGE + sB[i], b + (size_t)(lrow + 64 * i) * K_DIM);
        }
        cp_commit();

        const uint32_t Ast = sb + (uint32_t)(k & 3) * STAGE_BYTES;
        const uint32_t Bst = Ast + A_STAGE;

        #pragma unroll
        for (int ks = 0; ks < 4; ks++) {              // 4 x k32 per 128B chunk
            uint32_t af[4][4], bf[4][2];
            #pragma unroll
            for (int am = 0; am < 4; am++) {
                const uint32_t addr =
                    Ast + aRow128[am] + (uint32_t)((((ks << 1) + aKseg) ^ aMask[am]) << 4);
                LDSM_X4(af[am][0], af[am][1], af[am][2], af[am][3], addr);
            }
            #pragma unroll
            for (int bn = 0; bn < 4; bn++) {
                const uint32_t addr =
                    Bst + bRow128[bn] + (uint32_t)((((ks << 1) + bKseg) ^ bMask[bn]) << 4);
                LDSM_X2(bf[bn][0], bf[bn][1], addr);
            }
            #pragma unroll
            for (int am = 0; am < 4; am++)
                #pragma unroll
                for (int bn = 0; bn < 4; bn++)
                    IMMA(acc[am][bn], af[am], bf[bn]);
        }
    }

    // ---- epilogue: (acc + bias) * mean, float2 stores
    const float mean = mean_g;
    const int g  = lane >> 2;
    const int c2 = (lane & 3) * 2;
    #pragma unroll
    for (int am = 0; am < 4; am++) {
        const int row0 = m0 + wm * 64 + am * 16 + g;
        #pragma unroll
        for (int bn = 0; bn < 4; bn++) {
            const int col = n0 + wn * 32 + bn * 8 + c2;
            const float2 bb = *(const float2*)(bias + col);
            float2 v0, v1;
            v0.x = ((float)acc[am][bn][0] + bb.x) * mean;
            v0.y = ((float)acc[am][bn][1] + bb.y) * mean;
            v1.x = ((float)acc[am][bn][2] + bb.x) * mean;
            v1.y = ((float)acc[am][bn][3] + bb.y) * mean;
            *(float2*)(out + (size_t)row0 * O_COLS + col) = v0;
            *(float2*)(out + (size_t)(row0 + 8) * O_COLS + col) = v1;
        }
    }
}

// ============================================================
// launch: convert -> mean -> gemm (stream-ordered, graph-capturable)
// ============================================================
extern "C" void kernel_launch(void* const* d_in, const int* in_sizes, int n_in,
                              void* d_out, int out_size) {
    const float* x = (const float*)d_in[0];   // [8192, 4096]
    const float* W = (const float*)d_in[1];   // [4096, 4096]
    const float* b = (const float*)d_in[2];   // [4096]
    float* out = (float*)d_out;

    cudaFuncSetAttribute(imma_gemm_kernel,
                         cudaFuncAttributeMaxDynamicSharedMemorySize, SMEM_BYTES);

    convert_x_kernel<<<8192, 256>>>(x);
    convert_w_kernel<<<4096, 256>>>(W);
    reduce_mean_kernel<<<1, 1024>>>();

    dim3 grid(O_COLS / NT, N_ROWS / MT);      // (32, 32)
    imma_gemm_kernel<<<grid, GEMM_THREADS, SMEM_BYTES>>>(b, out);
}

// round 9
// speedup vs baseline: 2.0839x; 2.0839x over previous
#include <cuda_runtime.h>
#include <cstdint>

#define N_ROWS 8192
#define O_COLS 4096
#define K_DIM  4096
#define KWORDS 128          // K_DIM / 32

// ---- scratch (device globals; no dynamic allocation allowed) ----
__device__ __align__(16) unsigned xp_g[(size_t)N_ROWS * KWORDS];   // 4 MB
__device__ __align__(16) unsigned wp_g[(size_t)O_COLS * KWORDS];   // 2 MB
__device__ float psum_g[N_ROWS];
__device__ float mean_g;

// ============================================================
// Pack x rows into sign bits (bit=1 iff negative) + |x| row sums.
// One block per row, 128 threads.
// ============================================================
__global__ void pack_x_kernel(const float* __restrict__ x) {
    const int row  = blockIdx.x;
    const int tid  = threadIdx.x;
    const int lane = tid & 31;
    const int warp = tid >> 5;

    const float* xr = x + (size_t)row * K_DIM;
    float s = 0.f;

    #pragma unroll 4
    for (int it = 0; it < 32; it++) {
        const int w = warp * 32 + it;
        const float v = xr[w * 32 + lane];
        s += fabsf(v);
        const unsigned bits = __ballot_sync(0xffffffffu, __float_as_uint(v) >> 31);
        if (lane == 0) xp_g[(size_t)row * KWORDS + w] = bits;
    }

    __shared__ float red[128];
    red[tid] = s;
    __syncthreads();
    #pragma unroll
    for (int off = 64; off > 0; off >>= 1) {
        if (tid < off) red[tid] += red[tid + off];
        __syncthreads();
    }
    if (tid == 0) psum_g[row] = red[0];
}

__global__ void pack_w_kernel(const float* __restrict__ W) {
    const int row  = blockIdx.x;
    const int tid  = threadIdx.x;
    const int lane = tid & 31;
    const int warp = tid >> 5;

    const float* wr = W + (size_t)row * K_DIM;

    #pragma unroll 4
    for (int it = 0; it < 32; it++) {
        const int w = warp * 32 + it;
        const float v = wr[w * 32 + lane];
        const unsigned bits = __ballot_sync(0xffffffffu, __float_as_uint(v) >> 31);
        if (lane == 0) wp_g[(size_t)row * KWORDS + w] = bits;
    }
}

__global__ void reduce_mean_kernel() {
    __shared__ float red[1024];
    const int tid = threadIdx.x;
    float s = 0.f;
    for (int i = tid; i < N_ROWS; i += 1024) s += psum_g[i];
    red[tid] = s;
    __syncthreads();
    #pragma unroll
    for (int off = 512; off > 0; off >>= 1) {
        if (tid < off) red[tid] += red[tid + off];
        __syncthreads();
    }
    if (tid == 0) mean_g = red[0] * (1.0f / ((float)N_ROWS * (float)K_DIM));
}

// ============================================================
// XNOR-popcount GEMM v2: packed dual accumulators.
// Block: 64x64 tile, 256 threads, 4(m) x 4(o) per thread.
// Two o-columns share one 32-bit accumulator (lo/hi 16-bit fields):
//   pc = IMAD(popc_hi, 65536, popc_lo)   -> fma pipe
//   acc += pc0 + pc1 (two k-words)       -> one IADD3 on alu pipe
// count <= 4096 so no field overflow.
// dot = K - 2*count ; out = (dot + b) * mean
// ============================================================
#define BT 64
#define KW 16
#define KPAD 68

// force an IMAD (mad.lo with all-register operands; multiplier hidden from
// constant folding so ptxas cannot strength-reduce to LEA on the alu pipe)
__device__ __forceinline__ int imad_pack(int hi, int sh, int lo) {
    int r;
    asm("mad.lo.s32 %0, %1, %2, %3;" : "=r"(r) : "r"(hi), "r"(sh), "r"(lo));
    return r;
}

__global__ __launch_bounds__(256, 5)
void bgemm_kernel(const float* __restrict__ b, float* __restrict__ out) {
    __shared__ __align__(16) unsigned xs[KW][KPAD];
    __shared__ __align__(16) unsigned ws[KW][KPAD];

    const int tid = threadIdx.x;
    const int tx  = tid & 15;
    const int ty  = tid >> 4;
    const int o0  = blockIdx.x * BT;
    const int n0  = blockIdx.y * BT;

    const int lrow = tid >> 2;
    const int lq   = tid & 3;

    int sh;   // 0x10000 in a register, opaque to the compiler
    asm("mov.b32 %0, 0x10000;" : "=r"(sh));

    // accP[i][j2]: lo16 = count(col 2*j2), hi16 = count(col 2*j2+1)
    int accP[4][2];
    #pragma unroll
    for (int i = 0; i < 4; i++) { accP[i][0] = 0; accP[i][1] = 0; }

    for (int kw0 = 0; kw0 < KWORDS; kw0 += KW) {
        const uint4 xv = *(const uint4*)&xp_g[(size_t)(n0 + lrow) * KWORDS + kw0 + lq * 4];
        const uint4 wv = *(const uint4*)&wp_g[(size_t)(o0 + lrow) * KWORDS + kw0 + lq * 4];

        __syncthreads();
        xs[lq * 4 + 0][lrow] = xv.x;
        xs[lq * 4 + 1][lrow] = xv.y;
        xs[lq * 4 + 2][lrow] = xv.z;
        xs[lq * 4 + 3][lrow] = xv.w;
        ws[lq * 4 + 0][lrow] = wv.x;
        ws[lq * 4 + 1][lrow] = wv.y;
        ws[lq * 4 + 2][lrow] = wv.z;
        ws[lq * 4 + 3][lrow] = wv.w;
        __syncthreads();

        #pragma unroll
        for (int k = 0; k < KW; k += 2) {
            const uint4 a0 = *(const uint4*)&xs[k][ty * 4];
            const uint4 c0 = *(const uint4*)&ws[k][tx * 4];
            const uint4 a1 = *(const uint4*)&xs[k + 1][ty * 4];
            const uint4 c1 = *(const uint4*)&ws[k + 1][tx * 4];

            const unsigned ar0[4] = {a0.x, a0.y, a0.z, a0.w};
            const unsigned ar1[4] = {a1.x, a1.y, a1.z, a1.w};
            const unsigned cr0[4] = {c0.x, c0.y, c0.z, c0.w};
            const unsigned cr1[4] = {c1.x, c1.y, c1.z, c1.w};

            #pragma unroll
            for (int i = 0; i < 4; i++) {
                #pragma unroll
                for (int j2 = 0; j2 < 2; j2++) {
                    const int p0lo = __popc(ar0[i] ^ cr0[j2 * 2 + 0]);
                    const int p0hi = __popc(ar0[i] ^ cr0[j2 * 2 + 1]);
                    const int p1lo = __popc(ar1[i] ^ cr1[j2 * 2 + 0]);
                    const int p1hi = __popc(ar1[i] ^ cr1[j2 * 2 + 1]);
                    const int pc0 = imad_pack(p0hi, sh, p0lo);
                    const int pc1 = imad_pack(p1hi, sh, p1lo);
                    accP[i][j2] += pc0 + pc1;       // IADD3
                }
            }
        }
    }

    const float mean = mean_g;
    const int o_base = o0 + tx * 4;
    const int n_base = n0 + ty * 4;
    const float4 bb = *(const float4*)&b[o_base];

    #pragma unroll
    for (int i = 0; i < 4; i++) {
        const int c0 = accP[i][0] & 0xFFFF;
        const int c1 = (unsigned)accP[i][0] >> 16;
        const int c2 = accP[i][1] & 0xFFFF;
        const int c3 = (unsigned)accP[i][1] >> 16;
        float4 r;
        r.x = ((float)(K_DIM - 2 * c0) + bb.x) * mean;
        r.y = ((float)(K_DIM - 2 * c1) + bb.y) * mean;
        r.z = ((float)(K_DIM - 2 * c2) + bb.z) * mean;
        r.w = ((float)(K_DIM - 2 * c3) + bb.w) * mean;
        *(float4*)&out[(size_t)(n_base + i) * O_COLS + o_base] = r;
    }
}

// ============================================================
// launch: pack -> mean -> gemm (stream-ordered, graph-capturable)
// ============================================================
extern "C" void kernel_launch(void* const* d_in, const int* in_sizes, int n_in,
                              void* d_out, int out_size) {
    const float* x = (const float*)d_in[0];   // [8192, 4096]
    const float* W = (const float*)d_in[1];   // [4096, 4096]
    const float* b = (const float*)d_in[2];   // [4096]
    float* out = (float*)d_out;

    pack_x_kernel<<<N_ROWS, 128>>>(x);
    pack_w_kernel<<<O_COLS, 128>>>(W);
    reduce_mean_kernel<<<1, 1024>>>();

    dim3 grid(O_COLS / BT, N_ROWS / BT);      // (64, 128)
    bgemm_kernel<<<grid, 256>>>(b, out);
}